// round 1
// baseline (speedup 1.0000x reference)
#include <cuda_runtime.h>
#include <cuda_bf16.h>

// Problem constants
#define T_TOK 1024
#define D_IN  2048
#define O_SL  4096
#define TWO_O 8192
#define N_AD  4
#define PF    8

// Tiling
#define TM 128
#define TN 128
#define KC 16
#define MAX_MT 12

// Device-global scratch (no allocs allowed)
__device__ int d_perm[T_TOK];
__device__ int d_tile_a[MAX_MT];
__device__ int d_tile_start[MAX_MT];
__device__ int d_tile_rows[MAX_MT];
__device__ int d_ntiles;

// ---------------------------------------------------------------------------
// Kernel 1: group tokens by adapter, build M-tile metadata.
// Single block, 256 threads. Trivial cost (T=1024).
// ---------------------------------------------------------------------------
__global__ void group_tokens_kernel(const int* __restrict__ indices)
{
    __shared__ int cnt[N_AD], off[N_AD], cur[N_AD];
    int tid = threadIdx.x;
    if (tid < N_AD) cnt[tid] = 0;
    __syncthreads();

    for (int t = tid; t < T_TOK; t += blockDim.x)
        atomicAdd(&cnt[indices[t]], 1);
    __syncthreads();

    if (tid == 0) {
        int o = 0, nt = 0;
        for (int a = 0; a < N_AD; a++) {
            off[a] = o;
            cur[a] = 0;
            for (int r = 0; r < cnt[a]; r += TM) {
                d_tile_a[nt]     = a;
                d_tile_start[nt] = o + r;
                d_tile_rows[nt]  = min(TM, cnt[a] - r);
                nt++;
            }
            o += cnt[a];
        }
        d_ntiles = nt;
    }
    __syncthreads();

    for (int t = tid; t < T_TOK; t += blockDim.x) {
        int a = indices[t];
        int p = off[a] + atomicAdd(&cur[a], 1);
        d_perm[p] = t;
    }
}

// ---------------------------------------------------------------------------
// Kernel 2: fused GEMM  out[t, n] = x[t,:] . (Wb[n,:] + sc*(q - z)) + bias[n]
// Each block: one (M-tile, N-tile). M-tile is adapter-uniform, so the
// combined weight tile is built once per K-chunk in shared memory.
// 256 threads, 128x128 tile, 8x8 per-thread microtile, KC=16.
// ---------------------------------------------------------------------------
__global__ void __launch_bounds__(256, 2)
fused_gemm_kernel(const float* __restrict__ x,
                  const float* __restrict__ Wb,
                  const float* __restrict__ bias,
                  const int*   __restrict__ qw0,
                  const int*   __restrict__ qw1,
                  const int*   __restrict__ qz0,
                  const int*   __restrict__ qz1,
                  const float* __restrict__ sc0,
                  const float* __restrict__ sc1,
                  float*       __restrict__ out)
{
    const int mt = blockIdx.y;
    if (mt >= d_ntiles) return;
    const int nt = blockIdx.x;

    const int a     = d_tile_a[mt];
    const int start = d_tile_start[mt];
    const int rows  = d_tile_rows[mt];
    const int n0    = nt * TN;               // global output column base
    const int s     = n0 / O_SL;             // slice id (TN divides O_SL)
    const int ob    = n0 - s * O_SL;         // column base within slice

    const int*   qw = (s ? qw1 : qw0) + (size_t)a * O_SL * (D_IN / PF);
    const int*   qz = (s ? qz1 : qz0) + a * (O_SL / PF);
    const float* sc = (s ? sc1 : sc0) + a * O_SL;

    __shared__ float As[KC][TM];
    __shared__ float Bs[KC][TN];
    __shared__ int   tok[TM];

    const int tid = threadIdx.x;
    if (tid < TM) tok[tid] = (tid < rows) ? d_perm[start + tid] : -1;
    __syncthreads();

    const int tm = tid >> 4;     // 0..15
    const int tn = tid & 15;     // 0..15

    float acc[8][8];
#pragma unroll
    for (int i = 0; i < 8; i++)
#pragma unroll
        for (int j = 0; j < 8; j++) acc[i][j] = 0.0f;

    for (int k0 = 0; k0 < D_IN; k0 += KC) {
        // ---- load A tile (gathered token rows), layout As[k][m] ----
#pragma unroll
        for (int it = 0; it < 2; it++) {
            int i  = tid + it * 256;     // 0..511
            int mm = i & 127;
            int kg = i >> 7;             // 0..3
            int t  = tok[mm];
            float4 v = make_float4(0.f, 0.f, 0.f, 0.f);
            if (t >= 0)
                v = *reinterpret_cast<const float4*>(&x[t * D_IN + k0 + kg * 4]);
            As[kg * 4 + 0][mm] = v.x;
            As[kg * 4 + 1][mm] = v.y;
            As[kg * 4 + 2][mm] = v.z;
            As[kg * 4 + 3][mm] = v.w;
        }
        // ---- build combined B tile: Wb + sc*(q - z), layout Bs[k][n] ----
#pragma unroll
        for (int it = 0; it < 2; it++) {
            int i  = tid + it * 256;     // 0..511
            int nn = i >> 2;             // 0..127
            int kg = i & 3;              // 0..3
            int o  = ob + nn;            // row within slice
            int gn = n0 + nn;            // global output column
            int d  = k0 + kg * 4;

            float4 wb = *reinterpret_cast<const float4*>(&Wb[(size_t)gn * D_IN + d]);
            int   q32 = qw[o * (D_IN / PF) + (d >> 3)];
            int   sh  = (d & 7) * 4;     // 0 or 16
            float s_  = sc[o];
            int   zq  = (qz[o >> 3] >> ((o & 7) * 4)) & 0xF;
            float zf  = s_ * (float)zq;

            Bs[kg * 4 + 0][nn] = wb.x + s_ * (float)((q32 >> (sh + 0)) & 0xF) - zf;
            Bs[kg * 4 + 1][nn] = wb.y + s_ * (float)((q32 >> (sh + 4)) & 0xF) - zf;
            Bs[kg * 4 + 2][nn] = wb.z + s_ * (float)((q32 >> (sh + 8)) & 0xF) - zf;
            Bs[kg * 4 + 3][nn] = wb.w + s_ * (float)((q32 >> (sh + 12)) & 0xF) - zf;
        }
        __syncthreads();

        // ---- microkernel ----
#pragma unroll
        for (int kk = 0; kk < KC; kk++) {
            float ar[8], br[8];
#pragma unroll
            for (int i = 0; i < 8; i++) ar[i] = As[kk][tm * 8 + i];
#pragma unroll
            for (int j = 0; j < 8; j++) br[j] = Bs[kk][tn * 8 + j];
#pragma unroll
            for (int i = 0; i < 8; i++)
#pragma unroll
                for (int j = 0; j < 8; j++) acc[i][j] += ar[i] * br[j];
        }
        __syncthreads();
    }

    // ---- epilogue: scatter rows via perm, add bias ----
#pragma unroll
    for (int i = 0; i < 8; i++) {
        int mm = tm * 8 + i;
        int t  = tok[mm];
        if (t < 0) continue;
        float* orow = out + (size_t)t * TWO_O + n0;
#pragma unroll
        for (int j = 0; j < 8; j++) {
            int nn = tn * 8 + j;
            orow[nn] = acc[i][j] + bias[n0 + nn];
        }
    }
}

// ---------------------------------------------------------------------------
extern "C" void kernel_launch(void* const* d_in, const int* in_sizes, int n_in,
                              void* d_out, int out_size)
{
    const float* x    = (const float*)d_in[0];
    const float* Wb   = (const float*)d_in[1];
    const float* bias = (const float*)d_in[2];
    const int*   qw0  = (const int*)d_in[3];
    const int*   qw1  = (const int*)d_in[4];
    const int*   qz0  = (const int*)d_in[5];
    const int*   qz1  = (const int*)d_in[6];
    const float* sc0  = (const float*)d_in[7];
    const float* sc1  = (const float*)d_in[8];
    // d_in[9], d_in[10]: g_idx (all zeros, unused)
    const int* indices = (const int*)d_in[11];
    float* out = (float*)d_out;

    group_tokens_kernel<<<1, 256>>>(indices);
    fused_gemm_kernel<<<dim3(TWO_O / TN, MAX_MT), 256>>>(
        x, Wb, bias, qw0, qw1, qz0, qz1, sc0, sc1, out);
}

// round 3
// speedup vs baseline: 1.0033x; 1.0033x over previous
#include <cuda_runtime.h>
#include <cuda_bf16.h>

// Problem constants
#define T_TOK 1024
#define D_IN  2048
#define O_SL  4096
#define TWO_O 8192
#define N_AD  4
#define PF    8

// Tiling
#define TM 128
#define TN 128
#define KC 16
#define MAX_MT 12

// Device-global scratch (no allocs allowed)
__device__ int d_perm[T_TOK];
__device__ int d_tile_a[MAX_MT];
__device__ int d_tile_start[MAX_MT];
__device__ int d_tile_rows[MAX_MT];
__device__ int d_ntiles;

// ---------------------------------------------------------------------------
// Kernel 1: group tokens by adapter, build M-tile metadata.
// Single block, 256 threads. Trivial cost (T=1024).
// ---------------------------------------------------------------------------
__global__ void group_tokens_kernel(const int* __restrict__ indices)
{
    __shared__ int cnt[N_AD], off[N_AD], cur[N_AD];
    int tid = threadIdx.x;
    if (tid < N_AD) cnt[tid] = 0;
    __syncthreads();

    for (int t = tid; t < T_TOK; t += blockDim.x)
        atomicAdd(&cnt[indices[t]], 1);
    __syncthreads();

    if (tid == 0) {
        int o = 0, nt = 0;
        for (int a = 0; a < N_AD; a++) {
            off[a] = o;
            cur[a] = 0;
            for (int r = 0; r < cnt[a]; r += TM) {
                d_tile_a[nt]     = a;
                d_tile_start[nt] = o + r;
                d_tile_rows[nt]  = min(TM, cnt[a] - r);
                nt++;
            }
            o += cnt[a];
        }
        d_ntiles = nt;
    }
    __syncthreads();

    for (int t = tid; t < T_TOK; t += blockDim.x) {
        int a = indices[t];
        int p = off[a] + atomicAdd(&cur[a], 1);
        d_perm[p] = t;
    }
}

// ---------------------------------------------------------------------------
// Kernel 2: fused GEMM  out[t, n] = x[t,:] . (Wb[n,:] + sc*(q - z)) + bias[n]
// Each block: one (M-tile, N-tile). M-tile is adapter-uniform, so the
// combined weight tile is built once per K-chunk in shared memory.
// 256 threads, 128x128 tile, 8x8 per-thread microtile, KC=16.
// ---------------------------------------------------------------------------
__global__ void __launch_bounds__(256, 2)
fused_gemm_kernel(const float* __restrict__ x,
                  const float* __restrict__ Wb,
                  const float* __restrict__ bias,
                  const int*   __restrict__ qw0,
                  const int*   __restrict__ qw1,
                  const int*   __restrict__ qz0,
                  const int*   __restrict__ qz1,
                  const float* __restrict__ sc0,
                  const float* __restrict__ sc1,
                  float*       __restrict__ out)
{
    const int mt = blockIdx.y;
    if (mt >= d_ntiles) return;
    const int nt = blockIdx.x;

    const int a     = d_tile_a[mt];
    const int start = d_tile_start[mt];
    const int rows  = d_tile_rows[mt];
    const int n0    = nt * TN;               // global output column base
    const int s     = n0 / O_SL;             // slice id (TN divides O_SL)
    const int ob    = n0 - s * O_SL;         // column base within slice

    const int*   qw = (s ? qw1 : qw0) + (size_t)a * O_SL * (D_IN / PF);
    const int*   qz = (s ? qz1 : qz0) + a * (O_SL / PF);
    const float* sc = (s ? sc1 : sc0) + a * O_SL;

    __shared__ float As[KC][TM];
    __shared__ float Bs[KC][TN];
    __shared__ int   tok[TM];

    const int tid = threadIdx.x;
    if (tid < TM) tok[tid] = (tid < rows) ? d_perm[start + tid] : -1;
    __syncthreads();

    const int tm = tid >> 4;     // 0..15
    const int tn = tid & 15;     // 0..15

    float acc[8][8];
#pragma unroll
    for (int i = 0; i < 8; i++)
#pragma unroll
        for (int j = 0; j < 8; j++) acc[i][j] = 0.0f;

    for (int k0 = 0; k0 < D_IN; k0 += KC) {
        // ---- load A tile (gathered token rows), layout As[k][m] ----
#pragma unroll
        for (int it = 0; it < 2; it++) {
            int i  = tid + it * 256;     // 0..511
            int mm = i & 127;
            int kg = i >> 7;             // 0..3
            int t  = tok[mm];
            float4 v = make_float4(0.f, 0.f, 0.f, 0.f);
            if (t >= 0)
                v = *reinterpret_cast<const float4*>(&x[t * D_IN + k0 + kg * 4]);
            As[kg * 4 + 0][mm] = v.x;
            As[kg * 4 + 1][mm] = v.y;
            As[kg * 4 + 2][mm] = v.z;
            As[kg * 4 + 3][mm] = v.w;
        }
        // ---- build combined B tile: Wb + sc*(q - z), layout Bs[k][n] ----
#pragma unroll
        for (int it = 0; it < 2; it++) {
            int i  = tid + it * 256;     // 0..511
            int nn = i >> 2;             // 0..127
            int kg = i & 3;              // 0..3
            int o  = ob + nn;            // row within slice
            int gn = n0 + nn;            // global output column
            int d  = k0 + kg * 4;

            float4 wb = *reinterpret_cast<const float4*>(&Wb[(size_t)gn * D_IN + d]);
            int   q32 = qw[o * (D_IN / PF) + (d >> 3)];
            int   sh  = (d & 7) * 4;     // 0 or 16
            float s_  = sc[o];
            int   zq  = (qz[o >> 3] >> ((o & 7) * 4)) & 0xF;
            float zf  = s_ * (float)zq;

            Bs[kg * 4 + 0][nn] = wb.x + s_ * (float)((q32 >> (sh + 0)) & 0xF) - zf;
            Bs[kg * 4 + 1][nn] = wb.y + s_ * (float)((q32 >> (sh + 4)) & 0xF) - zf;
            Bs[kg * 4 + 2][nn] = wb.z + s_ * (float)((q32 >> (sh + 8)) & 0xF) - zf;
            Bs[kg * 4 + 3][nn] = wb.w + s_ * (float)((q32 >> (sh + 12)) & 0xF) - zf;
        }
        __syncthreads();

        // ---- microkernel ----
#pragma unroll
        for (int kk = 0; kk < KC; kk++) {
            float ar[8], br[8];
#pragma unroll
            for (int i = 0; i < 8; i++) ar[i] = As[kk][tm * 8 + i];
#pragma unroll
            for (int j = 0; j < 8; j++) br[j] = Bs[kk][tn * 8 + j];
#pragma unroll
            for (int i = 0; i < 8; i++)
#pragma unroll
                for (int j = 0; j < 8; j++) acc[i][j] += ar[i] * br[j];
        }
        __syncthreads();
    }

    // ---- epilogue: scatter rows via perm, add bias ----
#pragma unroll
    for (int i = 0; i < 8; i++) {
        int mm = tm * 8 + i;
        int t  = tok[mm];
        if (t < 0) continue;
        float* orow = out + (size_t)t * TWO_O + n0;
#pragma unroll
        for (int j = 0; j < 8; j++) {
            int nn = tn * 8 + j;
            orow[nn] = acc[i][j] + bias[n0 + nn];
        }
    }
}

// ---------------------------------------------------------------------------
extern "C" void kernel_launch(void* const* d_in, const int* in_sizes, int n_in,
                              void* d_out, int out_size)
{
    const float* x    = (const float*)d_in[0];
    const float* Wb   = (const float*)d_in[1];
    const float* bias = (const float*)d_in[2];
    const int*   qw0  = (const int*)d_in[3];
    const int*   qw1  = (const int*)d_in[4];
    const int*   qz0  = (const int*)d_in[5];
    const int*   qz1  = (const int*)d_in[6];
    const float* sc0  = (const float*)d_in[7];
    const float* sc1  = (const float*)d_in[8];
    // d_in[9], d_in[10]: g_idx (all zeros, unused)
    const int* indices = (const int*)d_in[11];
    float* out = (float*)d_out;

    group_tokens_kernel<<<1, 256>>>(indices);
    fused_gemm_kernel<<<dim3(TWO_O / TN, MAX_MT), 256>>>(
        x, Wb, bias, qw0, qw1, qz0, qz1, sc0, sc1, out);
}

// round 8
// speedup vs baseline: 2.4359x; 2.4279x over previous
#include <cuda_runtime.h>
#include <cstdint>
#include <cstddef>

// ---------------- problem constants ----------------
#define T_TOK 1024
#define D_IN  2048
#define O_SL  4096
#define TWO_O 8192
#define QWK   256           // D_IN/8 packed int32 per weight row
#define TM    128
#define TN    256
#define KCH   32
#define NCHUNK 64           // D_IN / KCH
#define NSTAGE 4
#define MAX_TILES 12

// ---------------- smem layout (floats, stride-padded rows) ----------------
#define RSTR   36                      // row stride in floats (conflict-free)
#define A_BYTES (TM * RSTR * 4)        // 18432
#define B_BYTES (TN * RSTR * 4)        // 36864
#define STAGE_B (A_BYTES + B_BYTES)    // 55296
#define SM_MISC 2048                   // bias(1024) + tok(512) + pad
#define SMEM_TOTAL (SM_MISC + NSTAGE * STAGE_B)   // 223232

// ---------------- device scratch ----------------
__device__ float d_xp[MAX_TILES * TM * D_IN];   // permuted, padded, tf32-rounded x
__device__ int d_perm[T_TOK];
__device__ int d_permp[MAX_TILES * TM];
__device__ int d_tile_a[MAX_TILES];
__device__ int d_ntiles;

// ---------------- helpers ----------------
__device__ __forceinline__ uint32_t smem_u32(const void* p){
    uint32_t a; asm("{ .reg .u64 t; cvta.to.shared.u64 t, %1; cvt.u32.u64 %0, t; }":"=r"(a):"l"(p)); return a;
}
__device__ __forceinline__ float tf32r(float f){
    uint32_t u; asm("cvt.rna.tf32.f32 %0, %1;" : "=r"(u) : "f"(f)); return __uint_as_float(u);
}
__device__ __forceinline__ void cp_async16(uint32_t dst, const void* src){
    asm volatile("cp.async.cg.shared.global [%0], [%1], 16;" :: "r"(dst), "l"(src) : "memory");
}
__device__ __forceinline__ void cp_commit(){ asm volatile("cp.async.commit_group;" ::: "memory"); }
template<int N> __device__ __forceinline__ void cp_wait(){ asm volatile("cp.async.wait_group %0;" :: "n"(N) : "memory"); }

__device__ __forceinline__ uint32_t lds_u32(uint32_t a){
    uint32_t v; asm("ld.shared.b32 %0, [%1];" : "=r"(v) : "r"(a)); return v;
}
__device__ __forceinline__ void mma_tf32(float* d, const uint32_t* a, const uint32_t* b){
    asm("mma.sync.aligned.m16n8k8.row.col.f32.tf32.tf32.f32 "
        "{%0,%1,%2,%3}, {%4,%5,%6,%7}, {%8,%9}, {%0,%1,%2,%3};"
        : "+f"(d[0]), "+f"(d[1]), "+f"(d[2]), "+f"(d[3])
        : "r"(a[0]), "r"(a[1]), "r"(a[2]), "r"(a[3]), "r"(b[0]), "r"(b[1]));
}

// ---------------------------------------------------------------------------
// Kernel 1: group tokens by adapter into 128-row tiles, build padded perm.
// ---------------------------------------------------------------------------
__global__ void group_tokens_kernel(const int* __restrict__ indices)
{
    __shared__ int cnt[4], off[4], cur[4];
    __shared__ int s_start[MAX_TILES], s_rows[MAX_TILES], s_nt;
    int tid = threadIdx.x;
    if (tid < 4) { cnt[tid] = 0; cur[tid] = 0; }
    __syncthreads();
    for (int t = tid; t < T_TOK; t += blockDim.x) atomicAdd(&cnt[indices[t]], 1);
    __syncthreads();
    if (tid == 0) {
        int o = 0, ntl = 0;
        for (int a = 0; a < 4; a++) {
            off[a] = o;
            for (int r = 0; r < cnt[a]; r += TM) {
                d_tile_a[ntl] = a;
                s_start[ntl]  = o + r;
                s_rows[ntl]   = min(TM, cnt[a] - r);
                ntl++;
            }
            o += cnt[a];
        }
        s_nt = ntl;
        d_ntiles = ntl;
    }
    __syncthreads();
    for (int t = tid; t < T_TOK; t += blockDim.x) {
        int a = indices[t];
        int p = off[a] + atomicAdd(&cur[a], 1);
        d_perm[p] = t;
    }
    __syncthreads();
    for (int idx = tid; idx < MAX_TILES * TM; idx += blockDim.x) {
        int tl = idx >> 7, r = idx & 127;
        int v = -1;
        if (tl < s_nt && r < s_rows[tl]) v = d_perm[s_start[tl] + r];
        d_permp[idx] = v;
    }
}

// ---------------------------------------------------------------------------
// Kernel 2: permuted / padded / tf32-rounded x copy (one block per row)
// ---------------------------------------------------------------------------
__global__ void build_xp_kernel(const float* __restrict__ x)
{
    int p = blockIdx.x;
    int t = d_permp[p];
    float4* dst = reinterpret_cast<float4*>(d_xp + (size_t)p * D_IN);
    if (t >= 0) {
        const float4* src = reinterpret_cast<const float4*>(x + (size_t)t * D_IN);
#pragma unroll
        for (int it = 0; it < 2; it++) {
            int j = threadIdx.x + it * 256;
            float4 v = src[j];
            v.x = tf32r(v.x); v.y = tf32r(v.y); v.z = tf32r(v.z); v.w = tf32r(v.w);
            dst[j] = v;
        }
    } else {
        float4 z = make_float4(0.f, 0.f, 0.f, 0.f);
#pragma unroll
        for (int it = 0; it < 2; it++) dst[threadIdx.x + it * 256] = z;
    }
}

// ---------------------------------------------------------------------------
// Kernel 3: mma.sync tf32 fused GEMM. Block = 128(M) x 256(N), 8 warps 2x4,
// warp tile 64x64, K-chunk 32, 4-stage cp.async + register-prefetch pipeline.
// ---------------------------------------------------------------------------
__global__ void __launch_bounds__(256, 1)
fused_mma_kernel(const float* __restrict__ Wb,
                 const float* __restrict__ bias,
                 const int*   __restrict__ qw0,
                 const int*   __restrict__ qw1,
                 const int*   __restrict__ qz0,
                 const int*   __restrict__ qz1,
                 const float* __restrict__ sc0,
                 const float* __restrict__ sc1,
                 float*       __restrict__ out)
{
    const int mt = blockIdx.y;
    if (mt >= d_ntiles) return;

    extern __shared__ char smem[];
    const uint32_t smb = smem_u32(smem);
    const int tid  = threadIdx.x;
    const int wid  = tid >> 5;
    const int lane = tid & 31;

    const int a  = d_tile_a[mt];
    const int n0 = blockIdx.x * TN;
    const int sl = (n0 >= O_SL);
    const int ob = n0 & (O_SL - 1);

    const int*   qw = (sl ? qw1 : qw0) + (size_t)a * O_SL * QWK;
    const int*   qz = (sl ? qz1 : qz0) + a * (O_SL / 8);
    const float* sc = (sl ? sc1 : sc0) + a * O_SL;

    // misc smem: bias[256] at 0, tok[128] at 1024
    {
        float* s_bias = reinterpret_cast<float*>(smem);
        s_bias[tid] = bias[n0 + tid];
        if (tid < TM) reinterpret_cast<int*>(smem + 1024)[tid] = d_permp[mt * TM + tid];
    }

    // -------- per-thread B metadata (hoisted) --------
    const int tq  = tid & 7;          // k-quad index 0..7 (covers k 4t..4t+3)
    const int nb0 = tid >> 3;         // base n (0..31), i-th slot n = nb0 + 32*i
    float scr[8];
    uint32_t zpack = 0;
#pragma unroll
    for (int i = 0; i < 8; i++) {
        int o = ob + nb0 + i * 32;
        scr[i] = __ldg(sc + o);
        uint32_t zq = ((uint32_t)__ldg(&qz[o >> 3]) >> ((o & 7) * 4)) & 0xFu;
        zpack |= zq << (i * 4);
    }
    const float* wp = Wb + (size_t)(n0 + nb0) * D_IN + tq * 4;
    const int*   qp = qw + (size_t)(ob + nb0) * QWK + (tq >> 1);   // FIX: +ob

    const float* xpt = d_xp + (size_t)mt * TM * D_IN;

    // -------- B prefetch registers --------
    float4 wbr[8];
    int    qr[8];

    auto ldg_b = [&](int c) {
        const int k0 = c * KCH;
#pragma unroll
        for (int i = 0; i < 8; i++) {
            wbr[i] = *reinterpret_cast<const float4*>(wp + (size_t)i * 32 * D_IN + k0);
            qr[i]  = __ldg(qp + i * 32 * QWK + (k0 >> 3));
        }
    };

#define STS_B(c) do {                                                          \
        const uint32_t bb = smb + SM_MISC + ((c) % NSTAGE) * STAGE_B + A_BYTES \
                          + (uint32_t)(nb0 * (RSTR*4) + tq * 16);              \
        const int shb = (tq & 1) * 16;                                         \
        _Pragma("unroll")                                                      \
        for (int i = 0; i < 8; i++) {                                          \
            float s_ = scr[i];                                                 \
            int   zq = (int)((zpack >> (i * 4)) & 0xFu);                       \
            int   q  = qr[i];                                                  \
            float v0 = tf32r(wbr[i].x + s_ * (float)(((q >> (shb + 0))  & 0xF) - zq)); \
            float v1 = tf32r(wbr[i].y + s_ * (float)(((q >> (shb + 4))  & 0xF) - zq)); \
            float v2 = tf32r(wbr[i].z + s_ * (float)(((q >> (shb + 8))  & 0xF) - zq)); \
            float v3 = tf32r(wbr[i].w + s_ * (float)(((q >> (shb + 12)) & 0xF) - zq)); \
            asm volatile("st.shared.v4.f32 [%0], {%1,%2,%3,%4};"               \
                :: "r"(bb + (uint32_t)(i * 32 * (RSTR*4))),                    \
                   "f"(v0), "f"(v1), "f"(v2), "f"(v3) : "memory");             \
        }                                                                      \
    } while (0)

#define CPA_A(c) do {                                                          \
        const uint32_t ab = smb + SM_MISC + ((c) % NSTAGE) * STAGE_B;          \
        const int k0 = (c) * KCH;                                              \
        _Pragma("unroll")                                                      \
        for (int j = 0; j < 4; j++) {                                          \
            int idx = tid + j * 256;                                           \
            int row = idx >> 3, f = idx & 7;                                   \
            cp_async16(ab + (uint32_t)(row * (RSTR*4) + f * 16),               \
                       xpt + (size_t)row * D_IN + k0 + f * 4);                 \
        }                                                                      \
    } while (0)

    // -------- prologue: fill stages 0..2 --------
    ldg_b(0);
    CPA_A(0); cp_commit();
    STS_B(0); ldg_b(1);
    CPA_A(1); cp_commit();
    STS_B(1); ldg_b(2);
    CPA_A(2); cp_commit();
    STS_B(2); ldg_b(3);

    // -------- accumulators --------
    float acc[4][8][4];
#pragma unroll
    for (int mf = 0; mf < 4; mf++)
#pragma unroll
        for (int nf = 0; nf < 8; nf++)
#pragma unroll
            for (int e = 0; e < 4; e++) acc[mf][nf][e] = 0.0f;

    const int wr = wid >> 2;      // 0..1 (M)
    const int wc = wid & 3;       // 0..3 (N)
    const uint32_t a_off = (uint32_t)((wr * 64 + (lane >> 2)) * (RSTR*4) + (lane & 3) * 4);
    const uint32_t b_off = (uint32_t)(A_BYTES + (wc * 64 + (lane >> 2)) * (RSTR*4) + (lane & 3) * 4);

    // -------- main loop --------
    for (int c = 0; c < NCHUNK; c++) {
        cp_wait<2>();
        __syncthreads();

        if (c + 3 < NCHUNK) { STS_B(c + 3); CPA_A(c + 3); }
        cp_commit();
        if (c + 4 < NCHUNK) ldg_b(c + 4);

        const uint32_t stage = smb + SM_MISC + (c % NSTAGE) * STAGE_B;
#pragma unroll
        for (int ks = 0; ks < 4; ks++) {
            const uint32_t koff = ks * 32;   // 8 floats * 4B
            uint32_t Af[4][4];
#pragma unroll
            for (int mf = 0; mf < 4; mf++) {
                uint32_t base = stage + a_off + mf * (16 * RSTR * 4) + koff;
                Af[mf][0] = lds_u32(base);
                Af[mf][1] = lds_u32(base + 8 * RSTR * 4);
                Af[mf][2] = lds_u32(base + 16);
                Af[mf][3] = lds_u32(base + 8 * RSTR * 4 + 16);
            }
            uint32_t Bf[8][2];
#pragma unroll
            for (int nf = 0; nf < 8; nf++) {
                uint32_t base = stage + b_off + nf * (8 * RSTR * 4) + koff;
                Bf[nf][0] = lds_u32(base);
                Bf[nf][1] = lds_u32(base + 16);
            }
#pragma unroll
            for (int mf = 0; mf < 4; mf++)
#pragma unroll
                for (int nf = 0; nf < 8; nf++)
                    mma_tf32(acc[mf][nf], Af[mf], Bf[nf]);
        }
    }

    // -------- epilogue --------
    __syncthreads();
    {
        const float* s_bias = reinterpret_cast<const float*>(smem);
        const int*   s_tok  = reinterpret_cast<const int*>(smem + 1024);
#pragma unroll
        for (int mf = 0; mf < 4; mf++) {
            int r_lo = wr * 64 + mf * 16 + (lane >> 2);
            int t_lo = s_tok[r_lo];
            int t_hi = s_tok[r_lo + 8];
#pragma unroll
            for (int nf = 0; nf < 8; nf++) {
                int ncol = n0 + wc * 64 + nf * 8 + 2 * (lane & 3);
                float b0 = s_bias[ncol - n0];
                float b1 = s_bias[ncol - n0 + 1];
                if (t_lo >= 0) {
                    float2 v = make_float2(acc[mf][nf][0] + b0, acc[mf][nf][1] + b1);
                    *reinterpret_cast<float2*>(out + (size_t)t_lo * TWO_O + ncol) = v;
                }
                if (t_hi >= 0) {
                    float2 v = make_float2(acc[mf][nf][2] + b0, acc[mf][nf][3] + b1);
                    *reinterpret_cast<float2*>(out + (size_t)t_hi * TWO_O + ncol) = v;
                }
            }
        }
    }
#undef STS_B
#undef CPA_A
}

// ---------------------------------------------------------------------------
extern "C" void kernel_launch(void* const* d_in, const int* in_sizes, int n_in,
                              void* d_out, int out_size)
{
    const float* x    = (const float*)d_in[0];
    const float* Wb   = (const float*)d_in[1];
    const float* bias = (const float*)d_in[2];
    const int*   qw0  = (const int*)d_in[3];
    const int*   qw1  = (const int*)d_in[4];
    const int*   qz0  = (const int*)d_in[5];
    const int*   qz1  = (const int*)d_in[6];
    const float* sc0  = (const float*)d_in[7];
    const float* sc1  = (const float*)d_in[8];
    const int* indices = (const int*)d_in[11];
    float* out = (float*)d_out;

    static int configured = 0;
    if (!configured) {
        cudaFuncSetAttribute(fused_mma_kernel,
                             cudaFuncAttributeMaxDynamicSharedMemorySize, SMEM_TOTAL);
        configured = 1;
    }

    group_tokens_kernel<<<1, 256>>>(indices);
    build_xp_kernel<<<MAX_TILES * TM, 256>>>(x);
    fused_mma_kernel<<<dim3(TWO_O / TN, MAX_TILES), 256, SMEM_TOTAL>>>(
        Wb, bias, qw0, qw1, qz0, qz1, sc0, sc1, out);
}

// round 9
// speedup vs baseline: 2.9562x; 1.2136x over previous
#include <cuda_runtime.h>
#include <cstdint>
#include <cstddef>

// ---------------- problem constants ----------------
#define T_TOK 1024
#define D_IN  2048
#define O_SL  4096
#define TWO_O 8192
#define QWK   256           // D_IN/8 packed int32 per weight row
#define TM    128
#define TN    256
#define KCH   32
#define NCHUNK 64           // D_IN / KCH
#define NSTAGE 4
#define MAX_TILES 12

// ---------------- smem layout (XOR-swizzled, no padding) ----------------
// Row = 32 floats = 128B = eight 16B groups; group g of row r stored at g^(r&7).
#define A_BYTES (TM * 128)             // 16384
#define B_BYTES (TN * 128)             // 32768
#define STAGE_B (A_BYTES + B_BYTES)    // 49152
#define SM_MISC 2048                   // bias(1024) + tok(512) + pad
#define SMEM_TOTAL (SM_MISC + NSTAGE * STAGE_B)   // 198656

// ---------------- device scratch ----------------
__device__ float d_xp[MAX_TILES * TM * D_IN];   // permuted, padded, tf32-rounded x
__device__ int d_perm[T_TOK];
__device__ int d_permp[MAX_TILES * TM];
__device__ int d_tile_a[MAX_TILES];
__device__ int d_ntiles;

// ---------------- helpers ----------------
__device__ __forceinline__ uint32_t smem_u32(const void* p){
    uint32_t a; asm("{ .reg .u64 t; cvta.to.shared.u64 t, %1; cvt.u32.u64 %0, t; }":"=r"(a):"l"(p)); return a;
}
__device__ __forceinline__ float tf32r(float f){
    uint32_t u; asm("cvt.rna.tf32.f32 %0, %1;" : "=r"(u) : "f"(f)); return __uint_as_float(u);
}
__device__ __forceinline__ void cp_async16(uint32_t dst, const void* src){
    asm volatile("cp.async.cg.shared.global [%0], [%1], 16;" :: "r"(dst), "l"(src) : "memory");
}
__device__ __forceinline__ void cp_commit(){ asm volatile("cp.async.commit_group;" ::: "memory"); }
template<int N> __device__ __forceinline__ void cp_wait(){ asm volatile("cp.async.wait_group %0;" :: "n"(N) : "memory"); }

__device__ __forceinline__ uint32_t lds_u32(uint32_t a){
    uint32_t v; asm("ld.shared.b32 %0, [%1];" : "=r"(v) : "r"(a)); return v;
}
__device__ __forceinline__ void mma_tf32(float* d, const uint32_t* a, const uint32_t* b){
    asm("mma.sync.aligned.m16n8k8.row.col.f32.tf32.tf32.f32 "
        "{%0,%1,%2,%3}, {%4,%5,%6,%7}, {%8,%9}, {%0,%1,%2,%3};"
        : "+f"(d[0]), "+f"(d[1]), "+f"(d[2]), "+f"(d[3])
        : "r"(a[0]), "r"(a[1]), "r"(a[2]), "r"(a[3]), "r"(b[0]), "r"(b[1]));
}

// ---------------------------------------------------------------------------
// Kernel 1: group tokens by adapter into 128-row tiles, build padded perm.
// ---------------------------------------------------------------------------
__global__ void group_tokens_kernel(const int* __restrict__ indices)
{
    __shared__ int cnt[4], off[4], cur[4];
    __shared__ int s_start[MAX_TILES], s_rows[MAX_TILES], s_nt;
    int tid = threadIdx.x;
    if (tid < 4) { cnt[tid] = 0; cur[tid] = 0; }
    __syncthreads();
    for (int t = tid; t < T_TOK; t += blockDim.x) atomicAdd(&cnt[indices[t]], 1);
    __syncthreads();
    if (tid == 0) {
        int o = 0, ntl = 0;
        for (int a = 0; a < 4; a++) {
            off[a] = o;
            for (int r = 0; r < cnt[a]; r += TM) {
                d_tile_a[ntl] = a;
                s_start[ntl]  = o + r;
                s_rows[ntl]   = min(TM, cnt[a] - r);
                ntl++;
            }
            o += cnt[a];
        }
        s_nt = ntl;
        d_ntiles = ntl;
    }
    __syncthreads();
    for (int t = tid; t < T_TOK; t += blockDim.x) {
        int a = indices[t];
        int p = off[a] + atomicAdd(&cur[a], 1);
        d_perm[p] = t;
    }
    __syncthreads();
    for (int idx = tid; idx < MAX_TILES * TM; idx += blockDim.x) {
        int tl = idx >> 7, r = idx & 127;
        int v = -1;
        if (tl < s_nt && r < s_rows[tl]) v = d_perm[s_start[tl] + r];
        d_permp[idx] = v;
    }
}

// ---------------------------------------------------------------------------
// Kernel 2: permuted / padded / tf32-rounded x copy (one block per row)
// ---------------------------------------------------------------------------
__global__ void build_xp_kernel(const float* __restrict__ x)
{
    int p = blockIdx.x;
    int t = d_permp[p];
    float4* dst = reinterpret_cast<float4*>(d_xp + (size_t)p * D_IN);
    if (t >= 0) {
        const float4* src = reinterpret_cast<const float4*>(x + (size_t)t * D_IN);
#pragma unroll
        for (int it = 0; it < 2; it++) {
            int j = threadIdx.x + it * 256;
            float4 v = src[j];
            v.x = tf32r(v.x); v.y = tf32r(v.y); v.z = tf32r(v.z); v.w = tf32r(v.w);
            dst[j] = v;
        }
    } else {
        float4 z = make_float4(0.f, 0.f, 0.f, 0.f);
#pragma unroll
        for (int it = 0; it < 2; it++) dst[threadIdx.x + it * 256] = z;
    }
}

// ---------------------------------------------------------------------------
// Kernel 3: mma.sync tf32 fused GEMM. Block = 128(M) x 256(N), 8 warps 2x4,
// warp tile 64x64, K-chunk 32, 4-stage cp.async pipeline, XOR-swizzled smem.
// Loop order: LDG(B,c+3) -> MMA(c) -> dequant/STS(c+3) so LDG hides under MMA.
// ---------------------------------------------------------------------------
__global__ void __launch_bounds__(256, 1)
fused_mma_kernel(const float* __restrict__ Wb,
                 const float* __restrict__ bias,
                 const int*   __restrict__ qw0,
                 const int*   __restrict__ qw1,
                 const int*   __restrict__ qz0,
                 const int*   __restrict__ qz1,
                 const float* __restrict__ sc0,
                 const float* __restrict__ sc1,
                 float*       __restrict__ out)
{
    const int mt = blockIdx.y;
    if (mt >= d_ntiles) return;

    extern __shared__ char smem[];
    const uint32_t smb = smem_u32(smem);
    const int tid  = threadIdx.x;
    const int wid  = tid >> 5;
    const int lane = tid & 31;

    const int a  = d_tile_a[mt];
    const int n0 = blockIdx.x * TN;
    const int sl = (n0 >= O_SL);
    const int ob = n0 & (O_SL - 1);

    const int*   qw = (sl ? qw1 : qw0) + (size_t)a * O_SL * QWK;
    const int*   qz = (sl ? qz1 : qz0) + a * (O_SL / 8);
    const float* sc = (sl ? sc1 : sc0) + a * O_SL;

    // misc smem: bias[256] at 0, tok[128] at 1024
    {
        float* s_bias = reinterpret_cast<float*>(smem);
        s_bias[tid] = bias[n0 + tid];
        if (tid < TM) reinterpret_cast<int*>(smem + 1024)[tid] = d_permp[mt * TM + tid];
    }

    // -------- per-thread B producer metadata (hoisted) --------
    const int tq  = tid & 7;          // 16B k-group index (words 4tq..4tq+3)
    const int nb0 = tid >> 3;         // base n (0..31), i-th slot n = nb0 + 32*i
    float scr[8];
    uint32_t zpack = 0;
#pragma unroll
    for (int i = 0; i < 8; i++) {
        int o = ob + nb0 + i * 32;
        scr[i] = __ldg(sc + o);
        uint32_t zq = ((uint32_t)__ldg(&qz[o >> 3]) >> ((o & 7) * 4)) & 0xFu;
        zpack |= zq << (i * 4);
    }
    const float* wp = Wb + (size_t)(n0 + nb0) * D_IN + tq * 4;
    const int*   qp = qw + (size_t)(ob + nb0) * QWK + (tq >> 1);
    // swizzled producer STS base (group tq ^ (nb0&7))
    const uint32_t b_sts = (uint32_t)(nb0 * 128 + ((tq ^ (nb0 & 7)) * 16));
    const int shb = (tq & 1) * 16;

    const float* xpt = d_xp + (size_t)mt * TM * D_IN;

#define STS_B(c, WBR, QR) do {                                                 \
        const uint32_t bb = smb + SM_MISC + ((c) % NSTAGE) * STAGE_B + A_BYTES \
                          + b_sts;                                             \
        _Pragma("unroll")                                                      \
        for (int i = 0; i < 8; i++) {                                          \
            float s_ = scr[i];                                                 \
            int   zq = (int)((zpack >> (i * 4)) & 0xFu);                       \
            int   q  = (QR)[i];                                                \
            float v0 = tf32r((WBR)[i].x + s_ * (float)(((q >> (shb + 0))  & 0xF) - zq)); \
            float v1 = tf32r((WBR)[i].y + s_ * (float)(((q >> (shb + 4))  & 0xF) - zq)); \
            float v2 = tf32r((WBR)[i].z + s_ * (float)(((q >> (shb + 8))  & 0xF) - zq)); \
            float v3 = tf32r((WBR)[i].w + s_ * (float)(((q >> (shb + 12)) & 0xF) - zq)); \
            asm volatile("st.shared.v4.f32 [%0], {%1,%2,%3,%4};"               \
                :: "r"(bb + (uint32_t)(i * 32 * 128)),                         \
                   "f"(v0), "f"(v1), "f"(v2), "f"(v3) : "memory");             \
        }                                                                      \
    } while (0)

#define CPA_A(c) do {                                                          \
        const uint32_t ab = smb + SM_MISC + ((c) % NSTAGE) * STAGE_B;          \
        const int k0 = (c) * KCH;                                              \
        _Pragma("unroll")                                                      \
        for (int j = 0; j < 4; j++) {                                          \
            int idx = tid + j * 256;                                           \
            int row = idx >> 3, f = idx & 7;                                   \
            cp_async16(ab + (uint32_t)(row * 128 + ((f ^ (row & 7)) * 16)),    \
                       xpt + (size_t)row * D_IN + k0 + f * 4);                 \
        }                                                                      \
    } while (0)

#define LDG_B(c, WBR, QR) do {                                                 \
        const int k0 = (c) * KCH;                                              \
        _Pragma("unroll")                                                      \
        for (int i = 0; i < 8; i++) {                                          \
            (WBR)[i] = *reinterpret_cast<const float4*>(wp + (size_t)i * 32 * D_IN + k0); \
            (QR)[i]  = __ldg(qp + i * 32 * QWK + (k0 >> 3));                   \
        }                                                                      \
    } while (0)

    // -------- prologue: fill stages 0..2 --------
    {
        float4 wbr[8]; int qr[8];
#pragma unroll
        for (int p = 0; p < 3; p++) {
            LDG_B(p, wbr, qr);
            STS_B(p, wbr, qr);
            CPA_A(p);
            cp_commit();
        }
    }

    // -------- accumulators --------
    float acc[4][8][4];
#pragma unroll
    for (int mf = 0; mf < 4; mf++)
#pragma unroll
        for (int nf = 0; nf < 8; nf++)
#pragma unroll
            for (int e = 0; e < 4; e++) acc[mf][nf][e] = 0.0f;

    const int wr = wid >> 2;      // 0..1 (M)
    const int wc = wid & 3;       // 0..3 (N)
    const int qd = lane >> 2;     // quad row 0..7 (also the XOR key)
    const uint32_t a_base = (uint32_t)((wr * 64 + qd) * 128 + (lane & 3) * 4);
    const uint32_t b_base = (uint32_t)(A_BYTES + (wc * 64 + qd) * 128 + (lane & 3) * 4);

    // -------- main loop --------
    for (int c = 0; c < NCHUNK; c++) {
        cp_wait<2>();
        __syncthreads();

        // B globals for chunk c+3 (hidden under the MMA section below)
        float4 wbr[8]; int qr[8];
        const bool pf = (c + 3 < NCHUNK);
        if (pf) LDG_B(c + 3, wbr, qr);

        const uint32_t stage = smb + SM_MISC + (c % NSTAGE) * STAGE_B;
#pragma unroll
        for (int ks = 0; ks < 4; ks++) {
            const uint32_t g0 = (uint32_t)(((2 * ks + 0) ^ qd) * 16);
            const uint32_t g1 = (uint32_t)(((2 * ks + 1) ^ qd) * 16);
            uint32_t Af[4][4];
#pragma unroll
            for (int mf = 0; mf < 4; mf++) {
                uint32_t base = stage + a_base + mf * 2048;
                Af[mf][0] = lds_u32(base + g0);
                Af[mf][1] = lds_u32(base + 1024 + g0);
                Af[mf][2] = lds_u32(base + g1);
                Af[mf][3] = lds_u32(base + 1024 + g1);
            }
            uint32_t Bf[8][2];
#pragma unroll
            for (int nf = 0; nf < 8; nf++) {
                uint32_t base = stage + b_base + nf * 1024;
                Bf[nf][0] = lds_u32(base + g0);
                Bf[nf][1] = lds_u32(base + g1);
            }
#pragma unroll
            for (int mf = 0; mf < 4; mf++)
#pragma unroll
                for (int nf = 0; nf < 8; nf++)
                    mma_tf32(acc[mf][nf], Af[mf], Bf[nf]);
        }

        // producers for chunk c+3
        if (pf) { STS_B(c + 3, wbr, qr); CPA_A(c + 3); }
        cp_commit();
    }

    // -------- epilogue --------
    __syncthreads();
    {
        const float* s_bias = reinterpret_cast<const float*>(smem);
        const int*   s_tok  = reinterpret_cast<const int*>(smem + 1024);
#pragma unroll
        for (int mf = 0; mf < 4; mf++) {
            int r_lo = wr * 64 + mf * 16 + qd;
            int t_lo = s_tok[r_lo];
            int t_hi = s_tok[r_lo + 8];
#pragma unroll
            for (int nf = 0; nf < 8; nf++) {
                int ncol = n0 + wc * 64 + nf * 8 + 2 * (lane & 3);
                float b0 = s_bias[ncol - n0];
                float b1 = s_bias[ncol - n0 + 1];
                if (t_lo >= 0) {
                    float2 v = make_float2(acc[mf][nf][0] + b0, acc[mf][nf][1] + b1);
                    *reinterpret_cast<float2*>(out + (size_t)t_lo * TWO_O + ncol) = v;
                }
                if (t_hi >= 0) {
                    float2 v = make_float2(acc[mf][nf][2] + b0, acc[mf][nf][3] + b1);
                    *reinterpret_cast<float2*>(out + (size_t)t_hi * TWO_O + ncol) = v;
                }
            }
        }
    }
#undef STS_B
#undef CPA_A
#undef LDG_B
}

// ---------------------------------------------------------------------------
extern "C" void kernel_launch(void* const* d_in, const int* in_sizes, int n_in,
                              void* d_out, int out_size)
{
    const float* x    = (const float*)d_in[0];
    const float* Wb   = (const float*)d_in[1];
    const float* bias = (const float*)d_in[2];
    const int*   qw0  = (const int*)d_in[3];
    const int*   qw1  = (const int*)d_in[4];
    const int*   qz0  = (const int*)d_in[5];
    const int*   qz1  = (const int*)d_in[6];
    const float* sc0  = (const float*)d_in[7];
    const float* sc1  = (const float*)d_in[8];
    const int* indices = (const int*)d_in[11];
    float* out = (float*)d_out;

    static int configured = 0;
    if (!configured) {
        cudaFuncSetAttribute(fused_mma_kernel,
                             cudaFuncAttributeMaxDynamicSharedMemorySize, SMEM_TOTAL);
        configured = 1;
    }

    group_tokens_kernel<<<1, 256>>>(indices);
    build_xp_kernel<<<MAX_TILES * TM, 256>>>(x);
    fused_mma_kernel<<<dim3(TWO_O / TN, MAX_TILES), 256, SMEM_TOTAL>>>(
        Wb, bias, qw0, qw1, qz0, qz1, sc0, sc1, out);
}